// round 15
// baseline (speedup 1.0000x reference)
#include <cuda_runtime.h>
#include <cuda_bf16.h>
#include <cuda_fp16.h>
#include <cstdint>
#include <cstddef>

// ---------------------------------------------------------------------------
// Shapes
// ---------------------------------------------------------------------------
#define B_      8
#define L_      1024
#define D_      1024
#define H_      16
#define DH_     64
#define DT_     256
#define HID_    4096
#define ROWS_   (B_ * L_)          // 8192
#define BH_     (B_ * H_)          // 128
#define K3D_    (3 * D_)           // 3072
#define K3H_    (3 * HID_)         // 12288

// ---------------------------------------------------------------------------
// Static device scratch
// ---------------------------------------------------------------------------
__device__ float d_gb[4][B_ * D_];
__device__ float d_x1  [ROWS_ * D_];
__device__ float d_gate[ROWS_ * HID_];

// bf16 GEMM operands (activations hi|hi|lo, weights hi|lo|hi)
__device__ __nv_bfloat16 d_xn3 [(size_t)ROWS_ * K3D_];
__device__ __nv_bfloat16 d_ao3 [(size_t)ROWS_ * K3D_];
__device__ __nv_bfloat16 d_ga3 [(size_t)ROWS_ * K3H_];
__device__ __nv_bfloat16 d_wqkv3[(size_t)(3 * D_) * K3D_];
__device__ __nv_bfloat16 d_wo3 [(size_t)D_ * K3D_];
__device__ __nv_bfloat16 d_wg3 [(size_t)HID_ * K3D_];
__device__ __nv_bfloat16 d_wh3 [(size_t)HID_ * K3D_];
__device__ __nv_bfloat16 d_wu3 [(size_t)D_ * K3H_];

// fp16 flash-attention operands
__device__ __half d_q3 [(size_t)BH_ * L_ * 192];   // hi|hi|lo
__device__ __half d_k3 [(size_t)BH_ * L_ * 192];   // hi|lo|hi
__device__ __half d_vh [(size_t)BH_ * L_ * 64];

// ---------------------------------------------------------------------------
// Helpers
// ---------------------------------------------------------------------------
__device__ __forceinline__ uint32_t smem_u32(const void* p) {
    uint32_t a;
    asm("{ .reg .u64 t; cvta.to.shared.u64 t, %1; cvt.u32.u64 %0, t; }" : "=r"(a) : "l"(p));
    return a;
}
__device__ __forceinline__ void cp16(uint32_t s, const void* g) {
    asm volatile("cp.async.cg.shared.global [%0], [%1], 16;" :: "r"(s), "l"(g));
}
__device__ __forceinline__ void cp_commit() {
    asm volatile("cp.async.commit_group;" ::: "memory");
}
__device__ __forceinline__ void cp_wait1() {
    asm volatile("cp.async.wait_group 1;" ::: "memory");
}
__device__ __forceinline__ void cp_wait0() {
    asm volatile("cp.async.wait_group 0;" ::: "memory");
}
__device__ __forceinline__ void ldsm4(uint32_t* r, uint32_t a) {
    asm volatile("ldmatrix.sync.aligned.m8n8.x4.shared.b16 {%0,%1,%2,%3}, [%4];"
                 : "=r"(r[0]), "=r"(r[1]), "=r"(r[2]), "=r"(r[3]) : "r"(a));
}
__device__ __forceinline__ void ldsm4t(uint32_t* r, uint32_t a) {
    asm volatile("ldmatrix.sync.aligned.m8n8.x4.trans.shared.b16 {%0,%1,%2,%3}, [%4];"
                 : "=r"(r[0]), "=r"(r[1]), "=r"(r[2]), "=r"(r[3]) : "r"(a));
}
__device__ __forceinline__ void mma_bf16(float* c, const uint32_t* a, uint32_t b0, uint32_t b1) {
    asm volatile("mma.sync.aligned.m16n8k16.row.col.f32.bf16.bf16.f32 "
                 "{%0,%1,%2,%3}, {%4,%5,%6,%7}, {%8,%9}, {%0,%1,%2,%3};"
                 : "+f"(c[0]), "+f"(c[1]), "+f"(c[2]), "+f"(c[3])
                 : "r"(a[0]), "r"(a[1]), "r"(a[2]), "r"(a[3]), "r"(b0), "r"(b1));
}
__device__ __forceinline__ void mma_f16(float* c, const uint32_t* a, uint32_t b0, uint32_t b1) {
    asm volatile("mma.sync.aligned.m16n8k16.row.col.f32.f16.f16.f32 "
                 "{%0,%1,%2,%3}, {%4,%5,%6,%7}, {%8,%9}, {%0,%1,%2,%3};"
                 : "+f"(c[0]), "+f"(c[1]), "+f"(c[2]), "+f"(c[3])
                 : "r"(a[0]), "r"(a[1]), "r"(a[2]), "r"(a[3]), "r"(b0), "r"(b1));
}
__device__ __forceinline__ float warpSum(float v) {
    #pragma unroll
    for (int o = 16; o; o >>= 1) v += __shfl_xor_sync(0xffffffffu, v, o);
    return v;
}
__device__ __forceinline__ void split2(float x, __nv_bfloat16& hi, __nv_bfloat16& lo) {
    hi = __float2bfloat16(x);
    lo = __float2bfloat16(x - __bfloat162float(hi));
}
__device__ __forceinline__ void split2h(float x, __half& hi, __half& lo) {
    hi = __float2half_rn(x);
    lo = __float2half_rn(x - __half2float(hi));
}
__device__ __forceinline__ uint32_t packh2(__half a, __half b) {
    __half2 t = {a, b};
    return *(uint32_t*)&t;
}
__device__ __forceinline__ uint32_t packh(float a, float b) {
    __half2 t = __floats2half2_rn(a, b);
    return *(uint32_t*)&t;
}

// ---------------------------------------------------------------------------
// 1) gamma/beta from t
// ---------------------------------------------------------------------------
__global__ void k_gamma_beta(const float* __restrict__ t,
                             const float* __restrict__ g1w, const float* __restrict__ g1b,
                             const float* __restrict__ b1w, const float* __restrict__ b1b,
                             const float* __restrict__ g2w, const float* __restrict__ g2b,
                             const float* __restrict__ b2w, const float* __restrict__ b2b) {
    int idx = blockIdx.x * blockDim.x + threadIdx.x;
    int sel = idx >> 13;
    int b   = (idx >> 10) & 7;
    int d   = idx & (D_ - 1);
    const float* w; const float* bias;
    if      (sel == 0) { w = g1w; bias = g1b; }
    else if (sel == 1) { w = b1w; bias = b1b; }
    else if (sel == 2) { w = g2w; bias = g2b; }
    else               { w = b2w; bias = b2b; }
    const float4* tr = (const float4*)(t + b * DT_);
    const float4* wr = (const float4*)(w + (size_t)d * DT_);
    float acc = 0.f;
    #pragma unroll
    for (int j = 0; j < DT_ / 4; j++) {
        float4 a = tr[j], c = wr[j];
        acc += a.x * c.x + a.y * c.y + a.z * c.z + a.w * c.w;
    }
    d_gb[sel][b * D_ + d] = acc + bias[d];
}

// ---------------------------------------------------------------------------
// 2) RMSNorm fused with bf16 triple conversion (hi|hi|lo)
// ---------------------------------------------------------------------------
__global__ void k_rmsnorm_cvt(const float* __restrict__ x, __nv_bfloat16* __restrict__ out3,
                              int selg, int selb) {
    __shared__ float sh[8];
    __shared__ float bcast;
    int row = blockIdx.x;
    int b   = row >> 10;
    int tid = threadIdx.x;
    const float4* xr = (const float4*)x + (size_t)row * (D_ / 4);
    float4 v = xr[tid];
    float ss = v.x * v.x + v.y * v.y + v.z * v.z + v.w * v.w;
    ss = warpSum(ss);
    if ((tid & 31) == 0) sh[tid >> 5] = ss;
    __syncthreads();
    if (tid < 32) {
        float a = (tid < 8) ? sh[tid] : 0.f;
        a = warpSum(a);
        if (tid == 0) bcast = a;
    }
    __syncthreads();
    float inv = rsqrtf(bcast * (1.0f / D_) + 1e-6f);
    const float4* g  = (const float4*)(d_gb[selg] + b * D_);
    const float4* bb = (const float4*)(d_gb[selb] + b * D_);
    float4 gv = g[tid], bv = bb[tid], r;
    r.x = gv.x * v.x * inv + bv.x;
    r.y = gv.y * v.y * inv + bv.y;
    r.z = gv.z * v.z * inv + bv.z;
    r.w = gv.w * v.w * inv + bv.w;
    __nv_bfloat16 hx, lx, hy, ly, hz, lz, hw, lw;
    split2(r.x, hx, lx); split2(r.y, hy, ly); split2(r.z, hz, lz); split2(r.w, hw, lw);
    __nv_bfloat16* o = out3 + (size_t)row * K3D_ + tid * 4;
    __nv_bfloat162 hi0 = {hx, hy}, hi1 = {hz, hw};
    __nv_bfloat162 lo0 = {lx, ly}, lo1 = {lz, lw};
    uint2 HI = make_uint2(*(uint32_t*)&hi0, *(uint32_t*)&hi1);
    uint2 LO = make_uint2(*(uint32_t*)&lo0, *(uint32_t*)&lo1);
    *(uint2*)(o)          = HI;
    *(uint2*)(o + D_)     = HI;
    *(uint2*)(o + 2 * D_) = LO;
}

// ---------------------------------------------------------------------------
// 3) ALL weight conversions in one launch (hi|lo|hi)
// ---------------------------------------------------------------------------
__device__ __forceinline__ void cvt3_store(float4 v, __nv_bfloat16* o, int K) {
    __nv_bfloat16 hx, lx, hy, ly, hz, lz, hw, lw;
    split2(v.x, hx, lx); split2(v.y, hy, ly); split2(v.z, hz, lz); split2(v.w, hw, lw);
    __nv_bfloat162 hi0 = {hx, hy}, hi1 = {hz, hw};
    __nv_bfloat162 lo0 = {lx, ly}, lo1 = {lz, lw};
    uint2 HI = make_uint2(*(uint32_t*)&hi0, *(uint32_t*)&hi1);
    uint2 LO = make_uint2(*(uint32_t*)&lo0, *(uint32_t*)&lo1);
    *(uint2*)(o)         = HI;
    *(uint2*)(o + K)     = LO;
    *(uint2*)(o + 2 * K) = HI;
}

__global__ void k_cvtw(const float* __restrict__ Wq, const float* __restrict__ Wk,
                       const float* __restrict__ Wv, const float* __restrict__ Wo,
                       const float* __restrict__ gatew, const float* __restrict__ hidw,
                       const float* __restrict__ outw,
                       __nv_bfloat16* __restrict__ wqkv3, __nv_bfloat16* __restrict__ wo3,
                       __nv_bfloat16* __restrict__ wg3,   __nv_bfloat16* __restrict__ wh3,
                       __nv_bfloat16* __restrict__ wu3) {
    int idx = blockIdx.x * blockDim.x + threadIdx.x;   // 0 .. 4M-1 float4
    if (idx < 4 * 262144) {
        int sel = idx >> 18;
        int i   = idx & 262143;
        int r   = i >> 8;
        int c4  = i & 255;
        const float* src = (sel == 0) ? Wq : (sel == 1) ? Wk : (sel == 2) ? Wv : Wo;
        float4 v = ((const float4*)src)[i];
        __nv_bfloat16* dst = (sel < 3) ? (wqkv3 + (size_t)sel * D_ * K3D_) : wo3;
        cvt3_store(v, dst + (size_t)r * K3D_ + c4 * 4, D_);
    } else {
        int i2   = idx - 4 * 262144;
        int sel2 = i2 >> 20;
        int i    = i2 & 1048575;
        if (sel2 < 2) {
            int r  = i >> 8;
            int c4 = i & 255;
            const float* src = sel2 ? hidw : gatew;
            float4 v = ((const float4*)src)[i];
            __nv_bfloat16* dst = sel2 ? wh3 : wg3;
            cvt3_store(v, dst + (size_t)r * K3D_ + c4 * 4, D_);
        } else {
            int r  = i >> 10;
            int c4 = i & 1023;
            float4 v = ((const float4*)outw)[i];
            cvt3_store(v, wu3 + (size_t)r * K3H_ + c4 * 4, HID_);
        }
    }
}

// ---------------------------------------------------------------------------
// 4) mma.sync bf16 GEMM: C[M,N] = A3[M,K3] . W3[N,K3]^T
//    256x128 block tile, BK=64, 8 warps (4x2), warp 64x64, 3-stage cp.async,
//    1 CTA/SM (256 regs/thread budget), double-buffered ldsm fragments.
//    MODE 0: fp32 out (+res)
//    MODE 1: swiglu(gate)*acc -> bf16 triple out3
//    MODE 2: QKV epilogue -> per-head fp16 flash operands q3/k3/vh
// ---------------------------------------------------------------------------
#define ASTRIDE   144
#define TILE_A    (256 * ASTRIDE)         // 36864
#define TILE_B    (128 * ASTRIDE)         // 18432
#define STAGEB    (TILE_A + TILE_B)       // 55296
#define GEMM_SMEM (3 * STAGEB)            // 165888

template<int MODE>
__global__ __launch_bounds__(256, 1) void k_gemm_mma(
        const __nv_bfloat16* __restrict__ A,
        const __nv_bfloat16* __restrict__ Bw,
        const float* __restrict__ res,      // residual (MODE0) or gate (MODE1)
        float* __restrict__ C,              // MODE0 out
        __nv_bfloat16* __restrict__ out3,   // MODE1 out (triple)
        __half* __restrict__ hq,            // MODE2 outs
        __half* __restrict__ hk,
        __half* __restrict__ hv,
        int N, int K3) {
    extern __shared__ char smem[];
    uint32_t sb = smem_u32(smem);
    int tid = threadIdx.x, lane = tid & 31, wid = tid >> 5;
    int wm = wid >> 1, wn = wid & 1;                 // 4 x 2 warp grid
    int bm = blockIdx.y * 256, bn = blockIdx.x * 128;

    // cp.async mapping: A one row per thread (8x16B), B half-row per thread (4x16B)
    const __nv_bfloat16* gA = A  + (size_t)(bm + tid) * K3;
    const __nv_bfloat16* gB = Bw + (size_t)(bn + (tid >> 1)) * K3 + (tid & 1) * 32;
    uint32_t aS = tid * ASTRIDE;
    uint32_t bS = TILE_A + (tid >> 1) * ASTRIDE + (tid & 1) * 64;

    uint32_t aOff = (uint32_t)((lane & 15) * ASTRIDE + (lane >> 4) * 16);
    uint32_t bOff = (uint32_t)(((lane & 7) + ((lane >> 4) & 1) * 8) * ASTRIDE
                               + ((lane >> 3) & 1) * 16);

    float acc[4][8][4] = {};
    int niter = K3 >> 6;

    #pragma unroll
    for (int p = 0; p < 2; p++) {
        uint32_t base = sb + p * STAGEB;
        const __nv_bfloat16* ag = gA + p * 64;
        const __nv_bfloat16* bg = gB + p * 64;
        #pragma unroll
        for (int i = 0; i < 8; i++) cp16(base + aS + i * 16, ag + i * 8);
        #pragma unroll
        for (int i = 0; i < 4; i++) cp16(base + bS + i * 16, bg + i * 8);
        cp_commit();
    }

    for (int it = 0; it < niter; it++) {
        cp_wait1();
        __syncthreads();
        int nx = it + 2;
        if (nx < niter) {
            uint32_t base = sb + (nx % 3) * STAGEB;
            const __nv_bfloat16* ag = gA + nx * 64;
            const __nv_bfloat16* bg = gB + nx * 64;
            #pragma unroll
            for (int i = 0; i < 8; i++) cp16(base + aS + i * 16, ag + i * 8);
            #pragma unroll
            for (int i = 0; i < 4; i++) cp16(base + bS + i * 16, bg + i * 8);
        }
        cp_commit();

        uint32_t Ab = sb + (it % 3) * STAGEB;
        uint32_t Bb = Ab + TILE_A;
        uint32_t af[2][4][4], bf[2][4][4];
        // preload ks=0 fragments
        #pragma unroll
        for (int am = 0; am < 4; am++)
            ldsm4(af[0][am], Ab + (wm * 64 + am * 16) * ASTRIDE + aOff);
        #pragma unroll
        for (int bg2 = 0; bg2 < 4; bg2++)
            ldsm4(bf[0][bg2], Bb + (wn * 64 + bg2 * 16) * ASTRIDE + bOff);
        #pragma unroll
        for (int ks = 0; ks < 4; ks++) {
            int cur = ks & 1, nxt = cur ^ 1;
            if (ks < 3) {
                #pragma unroll
                for (int am = 0; am < 4; am++)
                    ldsm4(af[nxt][am], Ab + (wm * 64 + am * 16) * ASTRIDE + (ks + 1) * 32 + aOff);
                #pragma unroll
                for (int bg2 = 0; bg2 < 4; bg2++)
                    ldsm4(bf[nxt][bg2], Bb + (wn * 64 + bg2 * 16) * ASTRIDE + (ks + 1) * 32 + bOff);
            }
            #pragma unroll
            for (int am = 0; am < 4; am++)
                #pragma unroll
                for (int bnn = 0; bnn < 8; bnn++)
                    mma_bf16(acc[am][bnn], af[cur][am],
                             bf[cur][bnn >> 1][(bnn & 1) * 2], bf[cur][bnn >> 1][(bnn & 1) * 2 + 1]);
        }
    }

    int g = lane >> 2;
    int mbase = bm + wm * 64;
    int nbase = bn + wn * 64 + (lane & 3) * 2;
    #pragma unroll
    for (int am = 0; am < 4; am++) {
        #pragma unroll
        for (int bnn = 0; bnn < 8; bnn++) {
            int row0 = mbase + am * 16 + g;
            int col  = nbase + bnn * 8;
            size_t o0 = (size_t)row0 * N + col;
            size_t o1 = (size_t)(row0 + 8) * N + col;
            float2 v0 = {acc[am][bnn][0], acc[am][bnn][1]};
            float2 v1 = {acc[am][bnn][2], acc[am][bnn][3]};
            if (MODE == 0) {
                if (res) {
                    float2 r0 = *(const float2*)(res + o0);
                    float2 r1 = *(const float2*)(res + o1);
                    v0.x += r0.x; v0.y += r0.y;
                    v1.x += r1.x; v1.y += r1.y;
                }
                *(float2*)(C + o0) = v0;
                *(float2*)(C + o1) = v1;
            } else if (MODE == 1) {
                float2 g0 = *(const float2*)(res + o0);
                float2 g1 = *(const float2*)(res + o1);
                float a0 = g0.x / (1.f + __expf(-g0.x)) * v0.x;
                float a1 = g0.y / (1.f + __expf(-g0.y)) * v0.y;
                float a2 = g1.x / (1.f + __expf(-g1.x)) * v1.x;
                float a3 = g1.y / (1.f + __expf(-g1.y)) * v1.y;
                __nv_bfloat16 h0, l0, h1, l1, h2, l2, h3, l3;
                split2(a0, h0, l0); split2(a1, h1, l1);
                split2(a2, h2, l2); split2(a3, h3, l3);
                __nv_bfloat162 hp0 = {h0, h1}, lp0 = {l0, l1};
                __nv_bfloat162 hp1 = {h2, h3}, lp1 = {l2, l3};
                __nv_bfloat16* op0 = out3 + (size_t)row0 * 3 * N + col;
                __nv_bfloat16* op1 = out3 + (size_t)(row0 + 8) * 3 * N + col;
                *(uint32_t*)(op0)         = *(uint32_t*)&hp0;
                *(uint32_t*)(op0 + N)     = *(uint32_t*)&hp0;
                *(uint32_t*)(op0 + 2 * N) = *(uint32_t*)&lp0;
                *(uint32_t*)(op1)         = *(uint32_t*)&hp1;
                *(uint32_t*)(op1 + N)     = *(uint32_t*)&hp1;
                *(uint32_t*)(op1 + 2 * N) = *(uint32_t*)&lp1;
            } else {
                int sec = col >> 10;
                int h   = (col >> 6) & 15;
                int d   = col & 63;
                #pragma unroll
                for (int rr = 0; rr < 2; rr++) {
                    int row = rr ? (row0 + 8) : row0;
                    float vx = rr ? v1.x : v0.x;
                    float vy = rr ? v1.y : v0.y;
                    int bb2 = row >> 10, ll2 = row & 1023;
                    size_t hb = ((size_t)(bb2 * 16 + h)) * 1024 + ll2;
                    __half hhx, hlx, hhy, hly;
                    split2h(vx, hhx, hlx); split2h(vy, hhy, hly);
                    uint32_t HIp = packh2(hhx, hhy);
                    uint32_t LOp = packh2(hlx, hly);
                    if (sec == 0) {
                        __half* o = hq + hb * 192 + d;
                        *(uint32_t*)(o)       = HIp;
                        *(uint32_t*)(o + 64)  = HIp;
                        *(uint32_t*)(o + 128) = LOp;
                    } else if (sec == 1) {
                        __half* o = hk + hb * 192 + d;
                        *(uint32_t*)(o)       = HIp;
                        *(uint32_t*)(o + 64)  = LOp;
                        *(uint32_t*)(o + 128) = HIp;
                    } else {
                        *(uint32_t*)(hv + hb * 64 + d) = HIp;
                    }
                }
            }
        }
    }
}

// ---------------------------------------------------------------------------
// 5) fused flash attention (fp16 tensor core), writes d_ao3 (bf16 hi|hi|lo)
// ---------------------------------------------------------------------------
#define QSTR 400
#define VSTR 144
#define FL_QOFF 0
#define FL_KOFF 25600
#define FL_VOFF 76800
#define FLASH_SMEM 95232

__global__ __launch_bounds__(128) void k_flash(
        const __half* __restrict__ q3h, const __half* __restrict__ k3h,
        const __half* __restrict__ vhh, __nv_bfloat16* __restrict__ ao3) {
    extern __shared__ char smem[];
    uint32_t sb = smem_u32(smem);
    int tid = threadIdx.x, lane = tid & 31, w = tid >> 5;
    int qt = blockIdx.x, bh = blockIdx.y;
    int b = bh >> 4, h = bh & 15;
    const __half* qg = q3h + (size_t)bh * L_ * 192 + (size_t)(qt * 64) * 192;
    const __half* kg = k3h + (size_t)bh * L_ * 192;
    const __half* vg = vhh + (size_t)bh * L_ * 64;

    int lrow2 = tid >> 1;
    int lhalf = tid & 1;

    {
        uint32_t qs = sb + FL_QOFF + lrow2 * QSTR + lhalf * 192;
        const char* src = (const char*)(qg + (size_t)lrow2 * 192) + lhalf * 192;
        #pragma unroll
        for (int i = 0; i < 12; i++) cp16(qs + i * 16, src + i * 16);
    }
    auto loadKV = [&](int t, int buf) {
        uint32_t ks = sb + FL_KOFF + buf * 25600 + lrow2 * QSTR + lhalf * 192;
        const char* ksrc = (const char*)(kg + (size_t)(t * 64 + lrow2) * 192) + lhalf * 192;
        #pragma unroll
        for (int i = 0; i < 12; i++) cp16(ks + i * 16, ksrc + i * 16);
        uint32_t vs = sb + FL_VOFF + buf * 9216 + lrow2 * VSTR + lhalf * 64;
        const char* vsrc = (const char*)(vg + (size_t)(t * 64 + lrow2) * 64) + lhalf * 64;
        #pragma unroll
        for (int i = 0; i < 4; i++) cp16(vs + i * 16, vsrc + i * 16);
    };
    loadKV(0, 0); cp_commit();
    loadKV(1, 1); cp_commit();

    float qm[2] = {-1e30f, -1e30f};
    float ll[2] = {0.f, 0.f};
    float o[8][4] = {};
    uint32_t qf[12][4];
    uint32_t aAddrQ = sb + FL_QOFF + (w * 16 + (lane & 15)) * QSTR + (lane >> 4) * 16;
    uint32_t bOffK = ((lane & 7) + ((lane >> 4) & 1) * 8) * QSTR + ((lane >> 3) & 1) * 16;
    uint32_t vOffT = (lane & 15) * VSTR + (lane >> 4) * 16;

    for (int t = 0; t < 16; t++) {
        if (t < 15) cp_wait1(); else cp_wait0();
        __syncthreads();
        if (t == 0) {
            #pragma unroll
            for (int ks = 0; ks < 12; ks++) ldsm4(qf[ks], aAddrQ + ks * 32);
        }
        uint32_t Kb = sb + FL_KOFF + (t & 1) * 25600;
        uint32_t Vb = sb + FL_VOFF + (t & 1) * 9216;

        float s[8][4] = {};
        #pragma unroll
        for (int ks = 0; ks < 12; ks++) {
            #pragma unroll
            for (int nb2 = 0; nb2 < 4; nb2++) {
                uint32_t bf[4];
                ldsm4(bf, Kb + bOffK + nb2 * 16 * QSTR + ks * 32);
                mma_f16(s[nb2 * 2],     qf[ks], bf[0], bf[1]);
                mma_f16(s[nb2 * 2 + 1], qf[ks], bf[2], bf[3]);
            }
        }
        float mx0 = -1e30f, mx1 = -1e30f;
        #pragma unroll
        for (int nb = 0; nb < 8; nb++) {
            #pragma unroll
            for (int e = 0; e < 4; e++) s[nb][e] *= 0.125f;
            mx0 = fmaxf(mx0, fmaxf(s[nb][0], s[nb][1]));
            mx1 = fmaxf(mx1, fmaxf(s[nb][2], s[nb][3]));
        }
        mx0 = fmaxf(mx0, __shfl_xor_sync(0xffffffffu, mx0, 1));
        mx0 = fmaxf(mx0, __shfl_xor_sync(0xffffffffu, mx0, 2));
        mx1 = fmaxf(mx1, __shfl_xor_sync(0xffffffffu, mx1, 1));
        mx1 = fmaxf(mx1, __shfl_xor_sync(0xffffffffu, mx1, 2));
        float mn0 = fmaxf(qm[0], mx0), mn1 = fmaxf(qm[1], mx1);
        float cf0 = __expf(qm[0] - mn0), cf1 = __expf(qm[1] - mn1);
        qm[0] = mn0; qm[1] = mn1;
        float sum0 = 0.f, sum1 = 0.f;
        #pragma unroll
        for (int nb = 0; nb < 8; nb++) {
            s[nb][0] = __expf(s[nb][0] - mn0);
            s[nb][1] = __expf(s[nb][1] - mn0);
            s[nb][2] = __expf(s[nb][2] - mn1);
            s[nb][3] = __expf(s[nb][3] - mn1);
            sum0 += s[nb][0] + s[nb][1];
            sum1 += s[nb][2] + s[nb][3];
        }
        sum0 += __shfl_xor_sync(0xffffffffu, sum0, 1);
        sum0 += __shfl_xor_sync(0xffffffffu, sum0, 2);
        sum1 += __shfl_xor_sync(0xffffffffu, sum1, 1);
        sum1 += __shfl_xor_sync(0xffffffffu, sum1, 2);
        ll[0] = ll[0] * cf0 + sum0;
        ll[1] = ll[1] * cf1 + sum1;
        #pragma unroll
        for (int nb = 0; nb < 8; nb++) {
            o[nb][0] *= cf0; o[nb][1] *= cf0;
            o[nb][2] *= cf1; o[nb][3] *= cf1;
        }
        uint32_t pf[4][4];
        #pragma unroll
        for (int kb = 0; kb < 4; kb++) {
            pf[kb][0] = packh(s[2 * kb][0],     s[2 * kb][1]);
            pf[kb][1] = packh(s[2 * kb][2],     s[2 * kb][3]);
            pf[kb][2] = packh(s[2 * kb + 1][0], s[2 * kb + 1][1]);
            pf[kb][3] = packh(s[2 * kb + 1][2], s[2 * kb + 1][3]);
        }
        #pragma unroll
        for (int kb = 0; kb < 4; kb++) {
            #pragma unroll
            for (int nbp = 0; nbp < 4; nbp++) {
                uint32_t vf[4];
                ldsm4t(vf, Vb + vOffT + kb * 16 * VSTR + nbp * 32);
                mma_f16(o[nbp * 2],     pf[kb], vf[0], vf[1]);
                mma_f16(o[nbp * 2 + 1], pf[kb], vf[2], vf[3]);
            }
        }
        __syncthreads();
        if (t + 2 < 16) { loadKV(t + 2, t & 1); cp_commit(); }
    }

    int g = lane >> 2;
    float inv0 = 1.f / ll[0], inv1 = 1.f / ll[1];
    int lr0 = qt * 64 + w * 16 + g;
    size_t base0 = ((size_t)(b * 1024 + lr0)) * K3D_ + h * 64;
    size_t base1 = ((size_t)(b * 1024 + lr0 + 8)) * K3D_ + h * 64;
    #pragma unroll
    for (int nb = 0; nb < 8; nb++) {
        int c = nb * 8 + (lane & 3) * 2;
        float v0 = o[nb][0] * inv0, v1 = o[nb][1] * inv0;
        float v2 = o[nb][2] * inv1, v3 = o[nb][3] * inv1;
        __nv_bfloat16 h0, l0x, h1, l1x, h2, l2x, h3, l3x;
        split2(v0, h0, l0x); split2(v1, h1, l1x);
        split2(v2, h2, l2x); split2(v3, h3, l3x);
        __nv_bfloat162 hp0 = {h0, h1}, lp0 = {l0x, l1x};
        __nv_bfloat162 hp1 = {h2, h3}, lp1 = {l2x, l3x};
        *(uint32_t*)(ao3 + base0 + c)        = *(uint32_t*)&hp0;
        *(uint32_t*)(ao3 + base0 + 1024 + c) = *(uint32_t*)&hp0;
        *(uint32_t*)(ao3 + base0 + 2048 + c) = *(uint32_t*)&lp0;
        *(uint32_t*)(ao3 + base1 + c)        = *(uint32_t*)&hp1;
        *(uint32_t*)(ao3 + base1 + 1024 + c) = *(uint32_t*)&hp1;
        *(uint32_t*)(ao3 + base1 + 2048 + c) = *(uint32_t*)&lp1;
    }
}

// ---------------------------------------------------------------------------
// Host launcher
// ---------------------------------------------------------------------------
extern "C" void kernel_launch(void* const* d_in, const int* in_sizes, int n_in,
                              void* d_out, int out_size) {
    const float* x     = (const float*)d_in[0];
    const float* t     = (const float*)d_in[1];
    const float* Wq    = (const float*)d_in[2];
    const float* Wk    = (const float*)d_in[3];
    const float* Wv    = (const float*)d_in[4];
    const float* Wo    = (const float*)d_in[5];
    const float* g1w   = (const float*)d_in[6];
    const float* g1b   = (const float*)d_in[7];
    const float* b1w   = (const float*)d_in[8];
    const float* b1b   = (const float*)d_in[9];
    const float* g2w   = (const float*)d_in[10];
    const float* g2b   = (const float*)d_in[11];
    const float* b2w   = (const float*)d_in[12];
    const float* b2b   = (const float*)d_in[13];
    const float* gatew = (const float*)d_in[14];
    const float* hidw  = (const float*)d_in[15];
    const float* outw  = (const float*)d_in[16];
    float* out = (float*)d_out;

    float *x1, *gate;
    __nv_bfloat16 *xn3, *ao3, *ga3, *wqkv3, *wo3, *wg3, *wh3, *wu3;
    __half *q3, *k3, *vh;
    cudaGetSymbolAddress((void**)&x1,    d_x1);
    cudaGetSymbolAddress((void**)&gate,  d_gate);
    cudaGetSymbolAddress((void**)&xn3,   d_xn3);
    cudaGetSymbolAddress((void**)&ao3,   d_ao3);
    cudaGetSymbolAddress((void**)&ga3,   d_ga3);
    cudaGetSymbolAddress((void**)&q3,    d_q3);
    cudaGetSymbolAddress((void**)&k3,    d_k3);
    cudaGetSymbolAddress((void**)&vh,    d_vh);
    cudaGetSymbolAddress((void**)&wqkv3, d_wqkv3);
    cudaGetSymbolAddress((void**)&wo3,   d_wo3);
    cudaGetSymbolAddress((void**)&wg3,   d_wg3);
    cudaGetSymbolAddress((void**)&wh3,   d_wh3);
    cudaGetSymbolAddress((void**)&wu3,   d_wu3);

    cudaFuncSetAttribute(k_gemm_mma<0>, cudaFuncAttributeMaxDynamicSharedMemorySize, GEMM_SMEM);
    cudaFuncSetAttribute(k_gemm_mma<1>, cudaFuncAttributeMaxDynamicSharedMemorySize, GEMM_SMEM);
    cudaFuncSetAttribute(k_gemm_mma<2>, cudaFuncAttributeMaxDynamicSharedMemorySize, GEMM_SMEM);
    cudaFuncSetAttribute(k_flash, cudaFuncAttributeMaxDynamicSharedMemorySize, FLASH_SMEM);

    // all weight conversions in one launch (4M float4s)
    k_cvtw<<<16384, 256>>>(Wq, Wk, Wv, Wo, gatew, hidw, outw,
                           wqkv3, wo3, wg3, wh3, wu3);

    // gamma/beta + norm1
    k_gamma_beta<<<128, 256>>>(t, g1w, g1b, b1w, b1b, g2w, g2b, b2w, b2b);
    k_rmsnorm_cvt<<<ROWS_, 256>>>(x, xn3, 0, 1);

    // fused QKV projection -> per-head fp16 flash operands (MODE 2)
    dim3 gqkv(3 * D_ / 128, ROWS_ / 256);   // (24, 32)
    dim3 gn1024(D_ / 128, ROWS_ / 256);     // (8, 32)
    dim3 gn4096(HID_ / 128, ROWS_ / 256);   // (32, 32)
    k_gemm_mma<2><<<gqkv, 256, GEMM_SMEM>>>(xn3, wqkv3, nullptr, nullptr, nullptr,
                                            q3, k3, vh, 3 * D_, K3D_);

    // flash attention (writes ao3 directly)
    k_flash<<<dim3(L_ / 64, BH_), 128, FLASH_SMEM>>>(q3, k3, vh, ao3);

    // output projection + residual
    k_gemm_mma<0><<<gn1024, 256, GEMM_SMEM>>>(ao3, wo3, x, x1, nullptr,
                                              nullptr, nullptr, nullptr, D_, K3D_);

    // norm2 + MLP (swiglu fused into hid GEMM epilogue)
    k_rmsnorm_cvt<<<ROWS_, 256>>>(x1, xn3, 2, 3);
    k_gemm_mma<0><<<gn4096, 256, GEMM_SMEM>>>(xn3, wg3, nullptr, gate, nullptr,
                                              nullptr, nullptr, nullptr, HID_, K3D_);
    k_gemm_mma<1><<<gn4096, 256, GEMM_SMEM>>>(xn3, wh3, gate, nullptr, ga3,
                                              nullptr, nullptr, nullptr, HID_, K3D_);
    k_gemm_mma<0><<<gn1024, 256, GEMM_SMEM>>>(ga3, wu3, x1, out, nullptr,
                                              nullptr, nullptr, nullptr, D_, K3H_);
}

// round 16
// speedup vs baseline: 1.5946x; 1.5946x over previous
#include <cuda_runtime.h>
#include <cuda_bf16.h>
#include <cuda_fp16.h>
#include <cstdint>
#include <cstddef>

// ---------------------------------------------------------------------------
// Shapes
// ---------------------------------------------------------------------------
#define B_      8
#define L_      1024
#define D_      1024
#define H_      16
#define DH_     64
#define DT_     256
#define HID_    4096
#define ROWS_   (B_ * L_)          // 8192
#define BH_     (B_ * H_)          // 128
#define K2D_    (2 * D_)           // 2048
#define K2H_    (2 * HID_)         // 8192

// ---------------------------------------------------------------------------
// Static device scratch
// ---------------------------------------------------------------------------
__device__ float d_gb[4][B_ * D_];
__device__ float d_x1  [ROWS_ * D_];
__device__ float d_gate[ROWS_ * HID_];

// fp16 2-term GEMM operands (activations [Ah|Al], weights [Wh|Wh])
__device__ __half d_xn2 [(size_t)ROWS_ * K2D_];
__device__ __half d_ao2 [(size_t)ROWS_ * K2D_];
__device__ __half d_ga2 [(size_t)ROWS_ * K2H_];
__device__ __half d_wqkv2[(size_t)(3 * D_) * K2D_];
__device__ __half d_wo2 [(size_t)D_ * K2D_];
__device__ __half d_wg2 [(size_t)HID_ * K2D_];
__device__ __half d_wh2 [(size_t)HID_ * K2D_];
__device__ __half d_wu2 [(size_t)D_ * K2H_];

// fp16 flash-attention operands
__device__ __half d_q3 [(size_t)BH_ * L_ * 192];   // hi|hi|lo
__device__ __half d_k3 [(size_t)BH_ * L_ * 192];   // hi|lo|hi
__device__ __half d_vh [(size_t)BH_ * L_ * 64];

// ---------------------------------------------------------------------------
// Helpers
// ---------------------------------------------------------------------------
__device__ __forceinline__ uint32_t smem_u32(const void* p) {
    uint32_t a;
    asm("{ .reg .u64 t; cvta.to.shared.u64 t, %1; cvt.u32.u64 %0, t; }" : "=r"(a) : "l"(p));
    return a;
}
__device__ __forceinline__ void cp16(uint32_t s, const void* g) {
    asm volatile("cp.async.cg.shared.global [%0], [%1], 16;" :: "r"(s), "l"(g));
}
__device__ __forceinline__ void cp_commit() {
    asm volatile("cp.async.commit_group;" ::: "memory");
}
__device__ __forceinline__ void cp_wait1() {
    asm volatile("cp.async.wait_group 1;" ::: "memory");
}
__device__ __forceinline__ void cp_wait0() {
    asm volatile("cp.async.wait_group 0;" ::: "memory");
}
__device__ __forceinline__ void ldsm4(uint32_t* r, uint32_t a) {
    asm volatile("ldmatrix.sync.aligned.m8n8.x4.shared.b16 {%0,%1,%2,%3}, [%4];"
                 : "=r"(r[0]), "=r"(r[1]), "=r"(r[2]), "=r"(r[3]) : "r"(a));
}
__device__ __forceinline__ void ldsm4t(uint32_t* r, uint32_t a) {
    asm volatile("ldmatrix.sync.aligned.m8n8.x4.trans.shared.b16 {%0,%1,%2,%3}, [%4];"
                 : "=r"(r[0]), "=r"(r[1]), "=r"(r[2]), "=r"(r[3]) : "r"(a));
}
__device__ __forceinline__ void mma_f16(float* c, const uint32_t* a, uint32_t b0, uint32_t b1) {
    asm volatile("mma.sync.aligned.m16n8k16.row.col.f32.f16.f16.f32 "
                 "{%0,%1,%2,%3}, {%4,%5,%6,%7}, {%8,%9}, {%0,%1,%2,%3};"
                 : "+f"(c[0]), "+f"(c[1]), "+f"(c[2]), "+f"(c[3])
                 : "r"(a[0]), "r"(a[1]), "r"(a[2]), "r"(a[3]), "r"(b0), "r"(b1));
}
__device__ __forceinline__ float warpSum(float v) {
    #pragma unroll
    for (int o = 16; o; o >>= 1) v += __shfl_xor_sync(0xffffffffu, v, o);
    return v;
}
__device__ __forceinline__ void split2(float x, __nv_bfloat16& hi, __nv_bfloat16& lo) {
    hi = __float2bfloat16(x);
    lo = __float2bfloat16(x - __bfloat162float(hi));
}
__device__ __forceinline__ void split2h(float x, __half& hi, __half& lo) {
    hi = __float2half_rn(x);
    lo = __float2half_rn(x - __half2float(hi));
}
__device__ __forceinline__ uint32_t packh2(__half a, __half b) {
    __half2 t = {a, b};
    return *(uint32_t*)&t;
}
__device__ __forceinline__ uint32_t packh(float a, float b) {
    __half2 t = __floats2half2_rn(a, b);
    return *(uint32_t*)&t;
}
// split float4 into packed hi (2x u32) and lo (2x u32) fp16 pairs
__device__ __forceinline__ void split4h(float4 v, uint2& HI, uint2& LO) {
    __half hx, lx, hy, ly, hz, lz, hw, lw;
    split2h(v.x, hx, lx); split2h(v.y, hy, ly);
    split2h(v.z, hz, lz); split2h(v.w, hw, lw);
    HI = make_uint2(packh2(hx, hy), packh2(hz, hw));
    LO = make_uint2(packh2(lx, ly), packh2(lz, lw));
}

// ---------------------------------------------------------------------------
// 1) gamma/beta from t
// ---------------------------------------------------------------------------
__global__ void k_gamma_beta(const float* __restrict__ t,
                             const float* __restrict__ g1w, const float* __restrict__ g1b,
                             const float* __restrict__ b1w, const float* __restrict__ b1b,
                             const float* __restrict__ g2w, const float* __restrict__ g2b,
                             const float* __restrict__ b2w, const float* __restrict__ b2b) {
    int idx = blockIdx.x * blockDim.x + threadIdx.x;
    int sel = idx >> 13;
    int b   = (idx >> 10) & 7;
    int d   = idx & (D_ - 1);
    const float* w; const float* bias;
    if      (sel == 0) { w = g1w; bias = g1b; }
    else if (sel == 1) { w = b1w; bias = b1b; }
    else if (sel == 2) { w = g2w; bias = g2b; }
    else               { w = b2w; bias = b2b; }
    const float4* tr = (const float4*)(t + b * DT_);
    const float4* wr = (const float4*)(w + (size_t)d * DT_);
    float acc = 0.f;
    #pragma unroll
    for (int j = 0; j < DT_ / 4; j++) {
        float4 a = tr[j], c = wr[j];
        acc += a.x * c.x + a.y * c.y + a.z * c.z + a.w * c.w;
    }
    d_gb[sel][b * D_ + d] = acc + bias[d];
}

// ---------------------------------------------------------------------------
// 2) RMSNorm fused with fp16 2-term conversion ([Ah|Al])
// ---------------------------------------------------------------------------
__global__ void k_rmsnorm_cvt(const float* __restrict__ x, __half* __restrict__ out2,
                              int selg, int selb) {
    __shared__ float sh[8];
    __shared__ float bcast;
    int row = blockIdx.x;
    int b   = row >> 10;
    int tid = threadIdx.x;
    const float4* xr = (const float4*)x + (size_t)row * (D_ / 4);
    float4 v = xr[tid];
    float ss = v.x * v.x + v.y * v.y + v.z * v.z + v.w * v.w;
    ss = warpSum(ss);
    if ((tid & 31) == 0) sh[tid >> 5] = ss;
    __syncthreads();
    if (tid < 32) {
        float a = (tid < 8) ? sh[tid] : 0.f;
        a = warpSum(a);
        if (tid == 0) bcast = a;
    }
    __syncthreads();
    float inv = rsqrtf(bcast * (1.0f / D_) + 1e-6f);
    const float4* g  = (const float4*)(d_gb[selg] + b * D_);
    const float4* bb = (const float4*)(d_gb[selb] + b * D_);
    float4 gv = g[tid], bv = bb[tid], r;
    r.x = gv.x * v.x * inv + bv.x;
    r.y = gv.y * v.y * inv + bv.y;
    r.z = gv.z * v.z * inv + bv.z;
    r.w = gv.w * v.w * inv + bv.w;
    uint2 HI, LO;
    split4h(r, HI, LO);
    __half* o = out2 + (size_t)row * K2D_ + tid * 4;
    *(uint2*)(o)      = HI;
    *(uint2*)(o + D_) = LO;
}

// ---------------------------------------------------------------------------
// 3) ALL weight conversions in one launch (fp16, [Wh|Wh] duplicated)
// ---------------------------------------------------------------------------
__device__ __forceinline__ void cvt2_store(float4 v, __half* o, int K) {
    uint2 HI = make_uint2(packh(v.x, v.y), packh(v.z, v.w));
    *(uint2*)(o)     = HI;
    *(uint2*)(o + K) = HI;
}

__global__ void k_cvtw(const float* __restrict__ Wq, const float* __restrict__ Wk,
                       const float* __restrict__ Wv, const float* __restrict__ Wo,
                       const float* __restrict__ gatew, const float* __restrict__ hidw,
                       const float* __restrict__ outw,
                       __half* __restrict__ wqkv2, __half* __restrict__ wo2,
                       __half* __restrict__ wg2,   __half* __restrict__ wh2,
                       __half* __restrict__ wu2) {
    int idx = blockIdx.x * blockDim.x + threadIdx.x;   // 0 .. 4M-1 float4
    if (idx < 4 * 262144) {
        int sel = idx >> 18;
        int i   = idx & 262143;
        int r   = i >> 8;
        int c4  = i & 255;
        const float* src = (sel == 0) ? Wq : (sel == 1) ? Wk : (sel == 2) ? Wv : Wo;
        float4 v = ((const float4*)src)[i];
        __half* dst = (sel < 3) ? (wqkv2 + (size_t)sel * D_ * K2D_) : wo2;
        cvt2_store(v, dst + (size_t)r * K2D_ + c4 * 4, D_);
    } else {
        int i2   = idx - 4 * 262144;
        int sel2 = i2 >> 20;
        int i    = i2 & 1048575;
        if (sel2 < 2) {
            int r  = i >> 8;
            int c4 = i & 255;
            const float* src = sel2 ? hidw : gatew;
            float4 v = ((const float4*)src)[i];
            __half* dst = sel2 ? wh2 : wg2;
            cvt2_store(v, dst + (size_t)r * K2D_ + c4 * 4, D_);
        } else {
            int r  = i >> 10;
            int c4 = i & 1023;
            float4 v = ((const float4*)outw)[i];
            cvt2_store(v, wu2 + (size_t)r * K2H_ + c4 * 4, HID_);
        }
    }
}

// ---------------------------------------------------------------------------
// 4) mma.sync fp16 GEMM: C[M,N] = A2[M,K2] . W2[N,K2]^T
//    128x128 tile, BK=64, 8 warps (2x4), warp 64x32, 3-stage cp.async
//    MODE 0: fp32 out (+res)
//    MODE 1: swiglu(gate)*acc -> fp16 2-term out2
//    MODE 2: QKV epilogue -> per-head fp16 flash operands q3/k3/vh
// ---------------------------------------------------------------------------
#define ASTRIDE   144
#define TILEB     (128 * ASTRIDE)         // 18432
#define GEMM_SMEM (3 * 2 * TILEB)         // 110592

template<int MODE>
__global__ __launch_bounds__(256, 2) void k_gemm_mma(
        const __half* __restrict__ A,
        const __half* __restrict__ Bw,
        const float* __restrict__ res,      // residual (MODE0) or gate (MODE1)
        float* __restrict__ C,              // MODE0 out
        __half* __restrict__ out2,          // MODE1 out (2-term)
        __half* __restrict__ hq,            // MODE2 outs
        __half* __restrict__ hk,
        __half* __restrict__ hv,
        int N, int K2) {
    extern __shared__ char smem[];
    uint32_t sb = smem_u32(smem);
    int tid = threadIdx.x, lane = tid & 31, wid = tid >> 5;
    int wm = wid >> 2, wn = wid & 3;
    int bm = blockIdx.y * 128, bn = blockIdx.x * 128;

    int crow = tid >> 1;
    int chalf = tid & 1;
    const __half* gA = A  + (size_t)(bm + crow) * K2 + chalf * 32;
    const __half* gB = Bw + (size_t)(bn + crow) * K2 + chalf * 32;
    uint32_t sOff = crow * ASTRIDE + chalf * 64;

    uint32_t aOff = (uint32_t)((lane & 15) * ASTRIDE + (lane >> 4) * 16);
    uint32_t bOff = (uint32_t)(((lane & 7) + ((lane >> 4) & 1) * 8) * ASTRIDE
                               + ((lane >> 3) & 1) * 16);

    float acc[4][4][4] = {};
    int niter = K2 >> 6;

    #pragma unroll
    for (int p = 0; p < 2; p++) {
        uint32_t as = sb + p * 2 * TILEB + sOff;
        const __half* ag = gA + p * 64;
        const __half* bg = gB + p * 64;
        #pragma unroll
        for (int i = 0; i < 4; i++) {
            cp16(as + i * 16,         ag + i * 8);
            cp16(as + TILEB + i * 16, bg + i * 8);
        }
        cp_commit();
    }

    for (int it = 0; it < niter; it++) {
        cp_wait1();
        __syncthreads();
        int nx = it + 2;
        if (nx < niter) {
            uint32_t as = sb + (nx % 3) * 2 * TILEB + sOff;
            const __half* ag = gA + nx * 64;
            const __half* bg = gB + nx * 64;
            #pragma unroll
            for (int i = 0; i < 4; i++) {
                cp16(as + i * 16,         ag + i * 8);
                cp16(as + TILEB + i * 16, bg + i * 8);
            }
        }
        cp_commit();

        uint32_t Ab = sb + (it % 3) * 2 * TILEB;
        uint32_t Bb = Ab + TILEB;
        #pragma unroll
        for (int ks = 0; ks < 4; ks++) {
            uint32_t a[4][4];
            #pragma unroll
            for (int am = 0; am < 4; am++)
                ldsm4(a[am], Ab + (wm * 64 + am * 16) * ASTRIDE + ks * 32 + aOff);
            uint32_t b[2][4];
            #pragma unroll
            for (int bg2 = 0; bg2 < 2; bg2++)
                ldsm4(b[bg2], Bb + (wn * 32 + bg2 * 16) * ASTRIDE + ks * 32 + bOff);
            #pragma unroll
            for (int am = 0; am < 4; am++)
                #pragma unroll
                for (int bnn = 0; bnn < 4; bnn++)
                    mma_f16(acc[am][bnn], a[am],
                            b[bnn >> 1][(bnn & 1) * 2], b[bnn >> 1][(bnn & 1) * 2 + 1]);
        }
    }

    int g = lane >> 2;
    int mbase = bm + wm * 64;
    int nbase = bn + wn * 32 + (lane & 3) * 2;
    #pragma unroll
    for (int am = 0; am < 4; am++) {
        #pragma unroll
        for (int bnn = 0; bnn < 4; bnn++) {
            int row0 = mbase + am * 16 + g;
            int col  = nbase + bnn * 8;
            size_t o0 = (size_t)row0 * N + col;
            size_t o1 = (size_t)(row0 + 8) * N + col;
            float2 v0 = {acc[am][bnn][0], acc[am][bnn][1]};
            float2 v1 = {acc[am][bnn][2], acc[am][bnn][3]};
            if (MODE == 0) {
                if (res) {
                    float2 r0 = *(const float2*)(res + o0);
                    float2 r1 = *(const float2*)(res + o1);
                    v0.x += r0.x; v0.y += r0.y;
                    v1.x += r1.x; v1.y += r1.y;
                }
                *(float2*)(C + o0) = v0;
                *(float2*)(C + o1) = v1;
            } else if (MODE == 1) {
                float2 g0 = *(const float2*)(res + o0);
                float2 g1 = *(const float2*)(res + o1);
                float a0 = g0.x / (1.f + __expf(-g0.x)) * v0.x;
                float a1 = g0.y / (1.f + __expf(-g0.y)) * v0.y;
                float a2 = g1.x / (1.f + __expf(-g1.x)) * v1.x;
                float a3 = g1.y / (1.f + __expf(-g1.y)) * v1.y;
                __half h0, l0, h1, l1, h2, l2, h3, l3;
                split2h(a0, h0, l0); split2h(a1, h1, l1);
                split2h(a2, h2, l2); split2h(a3, h3, l3);
                __half* op0 = out2 + (size_t)row0 * 2 * N + col;
                __half* op1 = out2 + (size_t)(row0 + 8) * 2 * N + col;
                *(uint32_t*)(op0)     = packh2(h0, h1);
                *(uint32_t*)(op0 + N) = packh2(l0, l1);
                *(uint32_t*)(op1)     = packh2(h2, h3);
                *(uint32_t*)(op1 + N) = packh2(l2, l3);
            } else {
                // MODE 2: col in [0,3072): sec|h|d, write fp16 flash operands
                int sec = col >> 10;
                int h   = (col >> 6) & 15;
                int d   = col & 63;
                #pragma unroll
                for (int rr = 0; rr < 2; rr++) {
                    int row = rr ? (row0 + 8) : row0;
                    float vx = rr ? v1.x : v0.x;
                    float vy = rr ? v1.y : v0.y;
                    int bb2 = row >> 10, ll2 = row & 1023;
                    size_t hb = ((size_t)(bb2 * 16 + h)) * 1024 + ll2;
                    __half hhx, hlx, hhy, hly;
                    split2h(vx, hhx, hlx); split2h(vy, hhy, hly);
                    uint32_t HIp = packh2(hhx, hhy);
                    uint32_t LOp = packh2(hlx, hly);
                    if (sec == 0) {
                        __half* o = hq + hb * 192 + d;
                        *(uint32_t*)(o)       = HIp;
                        *(uint32_t*)(o + 64)  = HIp;
                        *(uint32_t*)(o + 128) = LOp;
                    } else if (sec == 1) {
                        __half* o = hk + hb * 192 + d;
                        *(uint32_t*)(o)       = HIp;
                        *(uint32_t*)(o + 64)  = LOp;
                        *(uint32_t*)(o + 128) = HIp;
                    } else {
                        *(uint32_t*)(hv + hb * 64 + d) = HIp;
                    }
                }
            }
        }
    }
}

// ---------------------------------------------------------------------------
// 5) fused flash attention (fp16 tensor core), writes d_ao2 (fp16 [Ah|Al])
//    grid (qt=16, bh=128), 128 threads
// ---------------------------------------------------------------------------
#define QSTR 400
#define VSTR 144
#define FL_QOFF 0
#define FL_KOFF 25600
#define FL_VOFF 76800
#define FLASH_SMEM 95232

__global__ __launch_bounds__(128) void k_flash(
        const __half* __restrict__ q3h, const __half* __restrict__ k3h,
        const __half* __restrict__ vhh, __half* __restrict__ ao2) {
    extern __shared__ char smem[];
    uint32_t sb = smem_u32(smem);
    int tid = threadIdx.x, lane = tid & 31, w = tid >> 5;
    int qt = blockIdx.x, bh = blockIdx.y;
    int b = bh >> 4, h = bh & 15;
    const __half* qg = q3h + (size_t)bh * L_ * 192 + (size_t)(qt * 64) * 192;
    const __half* kg = k3h + (size_t)bh * L_ * 192;
    const __half* vg = vhh + (size_t)bh * L_ * 64;

    int lrow2 = tid >> 1;
    int lhalf = tid & 1;

    {
        uint32_t qs = sb + FL_QOFF + lrow2 * QSTR + lhalf * 192;
        const char* src = (const char*)(qg + (size_t)lrow2 * 192) + lhalf * 192;
        #pragma unroll
        for (int i = 0; i < 12; i++) cp16(qs + i * 16, src + i * 16);
    }
    auto loadKV = [&](int t, int buf) {
        uint32_t ks = sb + FL_KOFF + buf * 25600 + lrow2 * QSTR + lhalf * 192;
        const char* ksrc = (const char*)(kg + (size_t)(t * 64 + lrow2) * 192) + lhalf * 192;
        #pragma unroll
        for (int i = 0; i < 12; i++) cp16(ks + i * 16, ksrc + i * 16);
        uint32_t vs = sb + FL_VOFF + buf * 9216 + lrow2 * VSTR + lhalf * 64;
        const char* vsrc = (const char*)(vg + (size_t)(t * 64 + lrow2) * 64) + lhalf * 64;
        #pragma unroll
        for (int i = 0; i < 4; i++) cp16(vs + i * 16, vsrc + i * 16);
    };
    loadKV(0, 0); cp_commit();
    loadKV(1, 1); cp_commit();

    float qm[2] = {-1e30f, -1e30f};
    float ll[2] = {0.f, 0.f};
    float o[8][4] = {};
    uint32_t qf[12][4];
    uint32_t aAddrQ = sb + FL_QOFF + (w * 16 + (lane & 15)) * QSTR + (lane >> 4) * 16;
    uint32_t bOffK = ((lane & 7) + ((lane >> 4) & 1) * 8) * QSTR + ((lane >> 3) & 1) * 16;
    uint32_t vOffT = (lane & 15) * VSTR + (lane >> 4) * 16;

    for (int t = 0; t < 16; t++) {
        if (t < 15) cp_wait1(); else cp_wait0();
        __syncthreads();
        if (t == 0) {
            #pragma unroll
            for (int ks = 0; ks < 12; ks++) ldsm4(qf[ks], aAddrQ + ks * 32);
        }
        uint32_t Kb = sb + FL_KOFF + (t & 1) * 25600;
        uint32_t Vb = sb + FL_VOFF + (t & 1) * 9216;

        float s[8][4] = {};
        #pragma unroll
        for (int ks = 0; ks < 12; ks++) {
            #pragma unroll
            for (int nb2 = 0; nb2 < 4; nb2++) {
                uint32_t bf[4];
                ldsm4(bf, Kb + bOffK + nb2 * 16 * QSTR + ks * 32);
                mma_f16(s[nb2 * 2],     qf[ks], bf[0], bf[1]);
                mma_f16(s[nb2 * 2 + 1], qf[ks], bf[2], bf[3]);
            }
        }
        float mx0 = -1e30f, mx1 = -1e30f;
        #pragma unroll
        for (int nb = 0; nb < 8; nb++) {
            #pragma unroll
            for (int e = 0; e < 4; e++) s[nb][e] *= 0.125f;
            mx0 = fmaxf(mx0, fmaxf(s[nb][0], s[nb][1]));
            mx1 = fmaxf(mx1, fmaxf(s[nb][2], s[nb][3]));
        }
        mx0 = fmaxf(mx0, __shfl_xor_sync(0xffffffffu, mx0, 1));
        mx0 = fmaxf(mx0, __shfl_xor_sync(0xffffffffu, mx0, 2));
        mx1 = fmaxf(mx1, __shfl_xor_sync(0xffffffffu, mx1, 1));
        mx1 = fmaxf(mx1, __shfl_xor_sync(0xffffffffu, mx1, 2));
        float mn0 = fmaxf(qm[0], mx0), mn1 = fmaxf(qm[1], mx1);
        float cf0 = __expf(qm[0] - mn0), cf1 = __expf(qm[1] - mn1);
        qm[0] = mn0; qm[1] = mn1;
        float sum0 = 0.f, sum1 = 0.f;
        #pragma unroll
        for (int nb = 0; nb < 8; nb++) {
            s[nb][0] = __expf(s[nb][0] - mn0);
            s[nb][1] = __expf(s[nb][1] - mn0);
            s[nb][2] = __expf(s[nb][2] - mn1);
            s[nb][3] = __expf(s[nb][3] - mn1);
            sum0 += s[nb][0] + s[nb][1];
            sum1 += s[nb][2] + s[nb][3];
        }
        sum0 += __shfl_xor_sync(0xffffffffu, sum0, 1);
        sum0 += __shfl_xor_sync(0xffffffffu, sum0, 2);
        sum1 += __shfl_xor_sync(0xffffffffu, sum1, 1);
        sum1 += __shfl_xor_sync(0xffffffffu, sum1, 2);
        ll[0] = ll[0] * cf0 + sum0;
        ll[1] = ll[1] * cf1 + sum1;
        #pragma unroll
        for (int nb = 0; nb < 8; nb++) {
            o[nb][0] *= cf0; o[nb][1] *= cf0;
            o[nb][2] *= cf1; o[nb][3] *= cf1;
        }
        uint32_t pf[4][4];
        #pragma unroll
        for (int kb = 0; kb < 4; kb++) {
            pf[kb][0] = packh(s[2 * kb][0],     s[2 * kb][1]);
            pf[kb][1] = packh(s[2 * kb][2],     s[2 * kb][3]);
            pf[kb][2] = packh(s[2 * kb + 1][0], s[2 * kb + 1][1]);
            pf[kb][3] = packh(s[2 * kb + 1][2], s[2 * kb + 1][3]);
        }
        #pragma unroll
        for (int kb = 0; kb < 4; kb++) {
            #pragma unroll
            for (int nbp = 0; nbp < 4; nbp++) {
                uint32_t vf[4];
                ldsm4t(vf, Vb + vOffT + kb * 16 * VSTR + nbp * 32);
                mma_f16(o[nbp * 2],     pf[kb], vf[0], vf[1]);
                mma_f16(o[nbp * 2 + 1], pf[kb], vf[2], vf[3]);
            }
        }
        __syncthreads();
        if (t + 2 < 16) { loadKV(t + 2, t & 1); cp_commit(); }
    }

    int g = lane >> 2;
    float inv0 = 1.f / ll[0], inv1 = 1.f / ll[1];
    int lr0 = qt * 64 + w * 16 + g;
    size_t base0 = ((size_t)(b * 1024 + lr0)) * K2D_ + h * 64;
    size_t base1 = ((size_t)(b * 1024 + lr0 + 8)) * K2D_ + h * 64;
    #pragma unroll
    for (int nb = 0; nb < 8; nb++) {
        int c = nb * 8 + (lane & 3) * 2;
        float v0 = o[nb][0] * inv0, v1 = o[nb][1] * inv0;
        float v2 = o[nb][2] * inv1, v3 = o[nb][3] * inv1;
        __half h0, l0x, h1, l1x, h2, l2x, h3, l3x;
        split2h(v0, h0, l0x); split2h(v1, h1, l1x);
        split2h(v2, h2, l2x); split2h(v3, h3, l3x);
        *(uint32_t*)(ao2 + base0 + c)        = packh2(h0, h1);
        *(uint32_t*)(ao2 + base0 + 1024 + c) = packh2(l0x, l1x);
        *(uint32_t*)(ao2 + base1 + c)        = packh2(h2, h3);
        *(uint32_t*)(ao2 + base1 + 1024 + c) = packh2(l2x, l3x);
    }
}

// ---------------------------------------------------------------------------
// Host launcher
// ---------------------------------------------------------------------------
extern "C" void kernel_launch(void* const* d_in, const int* in_sizes, int n_in,
                              void* d_out, int out_size) {
    const float* x     = (const float*)d_in[0];
    const float* t     = (const float*)d_in[1];
    const float* Wq    = (const float*)d_in[2];
    const float* Wk    = (const float*)d_in[3];
    const float* Wv    = (const float*)d_in[4];
    const float* Wo    = (const float*)d_in[5];
    const float* g1w   = (const float*)d_in[6];
    const float* g1b   = (const float*)d_in[7];
    const float* b1w   = (const float*)d_in[8];
    const float* b1b   = (const float*)d_in[9];
    const float* g2w   = (const float*)d_in[10];
    const float* g2b   = (const float*)d_in[11];
    const float* b2w   = (const float*)d_in[12];
    const float* b2b   = (const float*)d_in[13];
    const float* gatew = (const float*)d_in[14];
    const float* hidw  = (const float*)d_in[15];
    const float* outw  = (const float*)d_in[16];
    float* out = (float*)d_out;

    float *x1, *gate;
    __half *xn2, *ao2, *ga2, *wqkv2, *wo2, *wg2, *wh2, *wu2, *q3, *k3, *vh;
    cudaGetSymbolAddress((void**)&x1,    d_x1);
    cudaGetSymbolAddress((void**)&gate,  d_gate);
    cudaGetSymbolAddress((void**)&xn2,   d_xn2);
    cudaGetSymbolAddress((void**)&ao2,   d_ao2);
    cudaGetSymbolAddress((void**)&ga2,   d_ga2);
    cudaGetSymbolAddress((void**)&q3,    d_q3);
    cudaGetSymbolAddress((void**)&k3,    d_k3);
    cudaGetSymbolAddress((void**)&vh,    d_vh);
    cudaGetSymbolAddress((void**)&wqkv2, d_wqkv2);
    cudaGetSymbolAddress((void**)&wo2,   d_wo2);
    cudaGetSymbolAddress((void**)&wg2,   d_wg2);
    cudaGetSymbolAddress((void**)&wh2,   d_wh2);
    cudaGetSymbolAddress((void**)&wu2,   d_wu2);

    cudaFuncSetAttribute(k_gemm_mma<0>, cudaFuncAttributeMaxDynamicSharedMemorySize, GEMM_SMEM);
    cudaFuncSetAttribute(k_gemm_mma<1>, cudaFuncAttributeMaxDynamicSharedMemorySize, GEMM_SMEM);
    cudaFuncSetAttribute(k_gemm_mma<2>, cudaFuncAttributeMaxDynamicSharedMemorySize, GEMM_SMEM);
    cudaFuncSetAttribute(k_flash, cudaFuncAttributeMaxDynamicSharedMemorySize, FLASH_SMEM);

    // all weight conversions in one launch (4M float4s)
    k_cvtw<<<16384, 256>>>(Wq, Wk, Wv, Wo, gatew, hidw, outw,
                           wqkv2, wo2, wg2, wh2, wu2);

    // gamma/beta + norm1
    k_gamma_beta<<<128, 256>>>(t, g1w, g1b, b1w, b1b, g2w, g2b, b2w, b2b);
    k_rmsnorm_cvt<<<ROWS_, 256>>>(x, xn2, 0, 1);

    // fused QKV projection -> per-head fp16 flash operands (MODE 2)
    dim3 gqkv(3 * D_ / 128, ROWS_ / 128);   // (24, 64)
    dim3 gn1024(D_ / 128, ROWS_ / 128);     // (8, 64)
    dim3 gn4096(HID_ / 128, ROWS_ / 128);   // (32, 64)
    k_gemm_mma<2><<<gqkv, 256, GEMM_SMEM>>>(xn2, wqkv2, nullptr, nullptr, nullptr,
                                            q3, k3, vh, 3 * D_, K2D_);

    // flash attention (writes ao2 directly)
    k_flash<<<dim3(L_ / 64, BH_), 128, FLASH_SMEM>>>(q3, k3, vh, ao2);

    // output projection + residual
    k_gemm_mma<0><<<gn1024, 256, GEMM_SMEM>>>(ao2, wo2, x, x1, nullptr,
                                              nullptr, nullptr, nullptr, D_, K2D_);

    // norm2 + MLP (swiglu fused into hid GEMM epilogue)
    k_rmsnorm_cvt<<<ROWS_, 256>>>(x1, xn2, 2, 3);
    k_gemm_mma<0><<<gn4096, 256, GEMM_SMEM>>>(xn2, wg2, nullptr, gate, nullptr,
                                              nullptr, nullptr, nullptr, HID_, K2D_);
    k_gemm_mma<1><<<gn4096, 256, GEMM_SMEM>>>(xn2, wh2, gate, nullptr, ga2,
                                              nullptr, nullptr, nullptr, HID_, K2D_);
    k_gemm_mma<0><<<gn1024, 256, GEMM_SMEM>>>(ga2, wu2, x1, out, nullptr,
                                              nullptr, nullptr, nullptr, D_, K2H_);
}

// round 17
// speedup vs baseline: 1.8592x; 1.1659x over previous
#include <cuda_runtime.h>
#include <cuda_bf16.h>
#include <cuda_fp16.h>
#include <cstdint>
#include <cstddef>

// ---------------------------------------------------------------------------
// Shapes
// ---------------------------------------------------------------------------
#define B_      8
#define L_      1024
#define D_      1024
#define H_      16
#define DH_     64
#define DT_     256
#define HID_    4096
#define ROWS_   (B_ * L_)          // 8192
#define BH_     (B_ * H_)          // 128
#define K2D_    (2 * D_)           // 2048

// ---------------------------------------------------------------------------
// Static device scratch
// ---------------------------------------------------------------------------
__device__ float d_gb[4][B_ * D_];
__device__ float d_x1  [ROWS_ * D_];
__device__ float d_gate[ROWS_ * HID_];

// fp16 GEMM operands
__device__ __half d_xn2 [(size_t)ROWS_ * K2D_];        // [Ah|Al]
__device__ __half d_ao1 [(size_t)ROWS_ * D_];          // attention out, 1-term
__device__ __half d_ga1 [(size_t)ROWS_ * HID_];        // swiglu out, 1-term
__device__ __half d_wqkv2[(size_t)(3 * D_) * K2D_];    // [Wh|Wh]
__device__ __half d_wo1 [(size_t)D_ * D_];             // 1-term
__device__ __half d_wg2 [(size_t)HID_ * K2D_];
__device__ __half d_wh2 [(size_t)HID_ * K2D_];
__device__ __half d_wu1 [(size_t)D_ * HID_];           // 1-term

// fp16 flash-attention operands
__device__ __half d_q3 [(size_t)BH_ * L_ * 192];   // hi|hi|lo
__device__ __half d_k3 [(size_t)BH_ * L_ * 192];   // hi|lo|hi
__device__ __half d_vh [(size_t)BH_ * L_ * 64];

// ---------------------------------------------------------------------------
// Helpers
// ---------------------------------------------------------------------------
__device__ __forceinline__ uint32_t smem_u32(const void* p) {
    uint32_t a;
    asm("{ .reg .u64 t; cvta.to.shared.u64 t, %1; cvt.u32.u64 %0, t; }" : "=r"(a) : "l"(p));
    return a;
}
__device__ __forceinline__ void cp16(uint32_t s, const void* g) {
    asm volatile("cp.async.cg.shared.global [%0], [%1], 16;" :: "r"(s), "l"(g));
}
__device__ __forceinline__ void cp_commit() {
    asm volatile("cp.async.commit_group;" ::: "memory");
}
__device__ __forceinline__ void cp_wait1() {
    asm volatile("cp.async.wait_group 1;" ::: "memory");
}
__device__ __forceinline__ void cp_wait0() {
    asm volatile("cp.async.wait_group 0;" ::: "memory");
}
__device__ __forceinline__ void ldsm4(uint32_t* r, uint32_t a) {
    asm volatile("ldmatrix.sync.aligned.m8n8.x4.shared.b16 {%0,%1,%2,%3}, [%4];"
                 : "=r"(r[0]), "=r"(r[1]), "=r"(r[2]), "=r"(r[3]) : "r"(a));
}
__device__ __forceinline__ void ldsm4t(uint32_t* r, uint32_t a) {
    asm volatile("ldmatrix.sync.aligned.m8n8.x4.trans.shared.b16 {%0,%1,%2,%3}, [%4];"
                 : "=r"(r[0]), "=r"(r[1]), "=r"(r[2]), "=r"(r[3]) : "r"(a));
}
__device__ __forceinline__ void mma_f16(float* c, const uint32_t* a, uint32_t b0, uint32_t b1) {
    asm volatile("mma.sync.aligned.m16n8k16.row.col.f32.f16.f16.f32 "
                 "{%0,%1,%2,%3}, {%4,%5,%6,%7}, {%8,%9}, {%0,%1,%2,%3};"
                 : "+f"(c[0]), "+f"(c[1]), "+f"(c[2]), "+f"(c[3])
                 : "r"(a[0]), "r"(a[1]), "r"(a[2]), "r"(a[3]), "r"(b0), "r"(b1));
}
__device__ __forceinline__ float warpSum(float v) {
    #pragma unroll
    for (int o = 16; o; o >>= 1) v += __shfl_xor_sync(0xffffffffu, v, o);
    return v;
}
__device__ __forceinline__ void split2h(float x, __half& hi, __half& lo) {
    hi = __float2half_rn(x);
    lo = __float2half_rn(x - __half2float(hi));
}
__device__ __forceinline__ uint32_t packh2(__half a, __half b) {
    __half2 t = {a, b};
    return *(uint32_t*)&t;
}
__device__ __forceinline__ uint32_t packh(float a, float b) {
    __half2 t = __floats2half2_rn(a, b);
    return *(uint32_t*)&t;
}
__device__ __forceinline__ void split4h(float4 v, uint2& HI, uint2& LO) {
    __half hx, lx, hy, ly, hz, lz, hw, lw;
    split2h(v.x, hx, lx); split2h(v.y, hy, ly);
    split2h(v.z, hz, lz); split2h(v.w, hw, lw);
    HI = make_uint2(packh2(hx, hy), packh2(hz, hw));
    LO = make_uint2(packh2(lx, ly), packh2(lz, lw));
}

// ---------------------------------------------------------------------------
// 1) gamma/beta from t
// ---------------------------------------------------------------------------
__global__ void k_gamma_beta(const float* __restrict__ t,
                             const float* __restrict__ g1w, const float* __restrict__ g1b,
                             const float* __restrict__ b1w, const float* __restrict__ b1b,
                             const float* __restrict__ g2w, const float* __restrict__ g2b,
                             const float* __restrict__ b2w, const float* __restrict__ b2b) {
    int idx = blockIdx.x * blockDim.x + threadIdx.x;
    int sel = idx >> 13;
    int b   = (idx >> 10) & 7;
    int d   = idx & (D_ - 1);
    const float* w; const float* bias;
    if      (sel == 0) { w = g1w; bias = g1b; }
    else if (sel == 1) { w = b1w; bias = b1b; }
    else if (sel == 2) { w = g2w; bias = g2b; }
    else               { w = b2w; bias = b2b; }
    const float4* tr = (const float4*)(t + b * DT_);
    const float4* wr = (const float4*)(w + (size_t)d * DT_);
    float acc = 0.f;
    #pragma unroll
    for (int j = 0; j < DT_ / 4; j++) {
        float4 a = tr[j], c = wr[j];
        acc += a.x * c.x + a.y * c.y + a.z * c.z + a.w * c.w;
    }
    d_gb[sel][b * D_ + d] = acc + bias[d];
}

// ---------------------------------------------------------------------------
// 2) RMSNorm fused with fp16 2-term conversion ([Ah|Al])
// ---------------------------------------------------------------------------
__global__ void k_rmsnorm_cvt(const float* __restrict__ x, __half* __restrict__ out2,
                              int selg, int selb) {
    __shared__ float sh[8];
    __shared__ float bcast;
    int row = blockIdx.x;
    int b   = row >> 10;
    int tid = threadIdx.x;
    const float4* xr = (const float4*)x + (size_t)row * (D_ / 4);
    float4 v = xr[tid];
    float ss = v.x * v.x + v.y * v.y + v.z * v.z + v.w * v.w;
    ss = warpSum(ss);
    if ((tid & 31) == 0) sh[tid >> 5] = ss;
    __syncthreads();
    if (tid < 32) {
        float a = (tid < 8) ? sh[tid] : 0.f;
        a = warpSum(a);
        if (tid == 0) bcast = a;
    }
    __syncthreads();
    float inv = rsqrtf(bcast * (1.0f / D_) + 1e-6f);
    const float4* g  = (const float4*)(d_gb[selg] + b * D_);
    const float4* bb = (const float4*)(d_gb[selb] + b * D_);
    float4 gv = g[tid], bv = bb[tid], r;
    r.x = gv.x * v.x * inv + bv.x;
    r.y = gv.y * v.y * inv + bv.y;
    r.z = gv.z * v.z * inv + bv.z;
    r.w = gv.w * v.w * inv + bv.w;
    uint2 HI, LO;
    split4h(r, HI, LO);
    __half* o = out2 + (size_t)row * K2D_ + tid * 4;
    *(uint2*)(o)      = HI;
    *(uint2*)(o + D_) = LO;
}

// ---------------------------------------------------------------------------
// 3) ALL weight conversions in one launch
//    wq/wk/wv: duplicated [Wh|Wh]; wo: single; gate/hid: duplicated; out: single
// ---------------------------------------------------------------------------
__device__ __forceinline__ void cvt2_store(float4 v, __half* o, int K) {
    uint2 HI = make_uint2(packh(v.x, v.y), packh(v.z, v.w));
    *(uint2*)(o)     = HI;
    *(uint2*)(o + K) = HI;
}
__device__ __forceinline__ void cvt1_store(float4 v, __half* o) {
    *(uint2*)o = make_uint2(packh(v.x, v.y), packh(v.z, v.w));
}

__global__ void k_cvtw(const float* __restrict__ Wq, const float* __restrict__ Wk,
                       const float* __restrict__ Wv, const float* __restrict__ Wo,
                       const float* __restrict__ gatew, const float* __restrict__ hidw,
                       const float* __restrict__ outw,
                       __half* __restrict__ wqkv2, __half* __restrict__ wo1,
                       __half* __restrict__ wg2,   __half* __restrict__ wh2,
                       __half* __restrict__ wu1) {
    int idx = blockIdx.x * blockDim.x + threadIdx.x;   // 0 .. 4M-1 float4
    if (idx < 4 * 262144) {
        int sel = idx >> 18;
        int i   = idx & 262143;
        int r   = i >> 8;
        int c4  = i & 255;
        if (sel < 3) {
            const float* src = (sel == 0) ? Wq : (sel == 1) ? Wk : Wv;
            float4 v = ((const float4*)src)[i];
            cvt2_store(v, wqkv2 + (size_t)sel * D_ * K2D_ + (size_t)r * K2D_ + c4 * 4, D_);
        } else {
            float4 v = ((const float4*)Wo)[i];
            cvt1_store(v, wo1 + (size_t)r * D_ + c4 * 4);
        }
    } else {
        int i2   = idx - 4 * 262144;
        int sel2 = i2 >> 20;
        int i    = i2 & 1048575;
        if (sel2 < 2) {
            int r  = i >> 8;
            int c4 = i & 255;
            const float* src = sel2 ? hidw : gatew;
            float4 v = ((const float4*)src)[i];
            __half* dst = sel2 ? wh2 : wg2;
            cvt2_store(v, dst + (size_t)r * K2D_ + c4 * 4, D_);
        } else {
            int r  = i >> 10;
            int c4 = i & 1023;
            float4 v = ((const float4*)outw)[i];
            cvt1_store(v, wu1 + (size_t)r * HID_ + c4 * 4);
        }
    }
}

// ---------------------------------------------------------------------------
// 4) mma.sync fp16 GEMM: C[M,N] = A[M,K] . W[N,K]^T
//    128x128 tile, BK=64, 8 warps (2x4), warp 64x32, 3-stage cp.async
//    MODE 0: fp32 out (+res)
//    MODE 1: swiglu(gate)*acc -> fp16 1-term out1
//    MODE 2: QKV epilogue -> per-head fp16 flash operands q3/k3/vh
// ---------------------------------------------------------------------------
#define ASTRIDE   144
#define TILEB     (128 * ASTRIDE)         // 18432
#define GEMM_SMEM (3 * 2 * TILEB)         // 110592

template<int MODE>
__global__ __launch_bounds__(256, 2) void k_gemm_mma(
        const __half* __restrict__ A,
        const __half* __restrict__ Bw,
        const float* __restrict__ res,      // residual (MODE0) or gate (MODE1)
        float* __restrict__ C,              // MODE0 out
        __half* __restrict__ out1,          // MODE1 out (1-term)
        __half* __restrict__ hq,            // MODE2 outs
        __half* __restrict__ hk,
        __half* __restrict__ hv,
        int N, int K) {
    extern __shared__ char smem[];
    uint32_t sb = smem_u32(smem);
    int tid = threadIdx.x, lane = tid & 31, wid = tid >> 5;
    int wm = wid >> 2, wn = wid & 3;
    int bm = blockIdx.y * 128, bn = blockIdx.x * 128;

    int crow = tid >> 1;
    int chalf = tid & 1;
    const __half* gA = A  + (size_t)(bm + crow) * K + chalf * 32;
    const __half* gB = Bw + (size_t)(bn + crow) * K + chalf * 32;
    uint32_t sOff = crow * ASTRIDE + chalf * 64;

    uint32_t aOff = (uint32_t)((lane & 15) * ASTRIDE + (lane >> 4) * 16);
    uint32_t bOff = (uint32_t)(((lane & 7) + ((lane >> 4) & 1) * 8) * ASTRIDE
                               + ((lane >> 3) & 1) * 16);

    float acc[4][4][4] = {};
    int niter = K >> 6;

    #pragma unroll
    for (int p = 0; p < 2; p++) {
        uint32_t as = sb + p * 2 * TILEB + sOff;
        const __half* ag = gA + p * 64;
        const __half* bg = gB + p * 64;
        #pragma unroll
        for (int i = 0; i < 4; i++) {
            cp16(as + i * 16,         ag + i * 8);
            cp16(as + TILEB + i * 16, bg + i * 8);
        }
        cp_commit();
    }

    for (int it = 0; it < niter; it++) {
        cp_wait1();
        __syncthreads();
        int nx = it + 2;
        if (nx < niter) {
            uint32_t as = sb + (nx % 3) * 2 * TILEB + sOff;
            const __half* ag = gA + nx * 64;
            const __half* bg = gB + nx * 64;
            #pragma unroll
            for (int i = 0; i < 4; i++) {
                cp16(as + i * 16,         ag + i * 8);
                cp16(as + TILEB + i * 16, bg + i * 8);
            }
        }
        cp_commit();

        uint32_t Ab = sb + (it % 3) * 2 * TILEB;
        uint32_t Bb = Ab + TILEB;
        #pragma unroll
        for (int ks = 0; ks < 4; ks++) {
            uint32_t a[4][4];
            #pragma unroll
            for (int am = 0; am < 4; am++)
                ldsm4(a[am], Ab + (wm * 64 + am * 16) * ASTRIDE + ks * 32 + aOff);
            uint32_t b[2][4];
            #pragma unroll
            for (int bg2 = 0; bg2 < 2; bg2++)
                ldsm4(b[bg2], Bb + (wn * 32 + bg2 * 16) * ASTRIDE + ks * 32 + bOff);
            #pragma unroll
            for (int am = 0; am < 4; am++)
                #pragma unroll
                for (int bnn = 0; bnn < 4; bnn++)
                    mma_f16(acc[am][bnn], a[am],
                            b[bnn >> 1][(bnn & 1) * 2], b[bnn >> 1][(bnn & 1) * 2 + 1]);
        }
    }

    int g = lane >> 2;
    int mbase = bm + wm * 64;
    int nbase = bn + wn * 32 + (lane & 3) * 2;
    #pragma unroll
    for (int am = 0; am < 4; am++) {
        #pragma unroll
        for (int bnn = 0; bnn < 4; bnn++) {
            int row0 = mbase + am * 16 + g;
            int col  = nbase + bnn * 8;
            size_t o0 = (size_t)row0 * N + col;
            size_t o1 = (size_t)(row0 + 8) * N + col;
            float2 v0 = {acc[am][bnn][0], acc[am][bnn][1]};
            float2 v1 = {acc[am][bnn][2], acc[am][bnn][3]};
            if (MODE == 0) {
                if (res) {
                    float2 r0 = *(const float2*)(res + o0);
                    float2 r1 = *(const float2*)(res + o1);
                    v0.x += r0.x; v0.y += r0.y;
                    v1.x += r1.x; v1.y += r1.y;
                }
                *(float2*)(C + o0) = v0;
                *(float2*)(C + o1) = v1;
            } else if (MODE == 1) {
                float2 g0 = *(const float2*)(res + o0);
                float2 g1 = *(const float2*)(res + o1);
                float a0 = g0.x / (1.f + __expf(-g0.x)) * v0.x;
                float a1 = g0.y / (1.f + __expf(-g0.y)) * v0.y;
                float a2 = g1.x / (1.f + __expf(-g1.x)) * v1.x;
                float a3 = g1.y / (1.f + __expf(-g1.y)) * v1.y;
                *(uint32_t*)(out1 + o0) = packh(a0, a1);
                *(uint32_t*)(out1 + o1) = packh(a2, a3);
            } else {
                // MODE 2: col in [0,3072): sec|h|d, write fp16 flash operands
                int sec = col >> 10;
                int h   = (col >> 6) & 15;
                int d   = col & 63;
                #pragma unroll
                for (int rr = 0; rr < 2; rr++) {
                    int row = rr ? (row0 + 8) : row0;
                    float vx = rr ? v1.x : v0.x;
                    float vy = rr ? v1.y : v0.y;
                    int bb2 = row >> 10, ll2 = row & 1023;
                    size_t hb = ((size_t)(bb2 * 16 + h)) * 1024 + ll2;
                    __half hhx, hlx, hhy, hly;
                    split2h(vx, hhx, hlx); split2h(vy, hhy, hly);
                    uint32_t HIp = packh2(hhx, hhy);
                    uint32_t LOp = packh2(hlx, hly);
                    if (sec == 0) {
                        __half* o = hq + hb * 192 + d;
                        *(uint32_t*)(o)       = HIp;
                        *(uint32_t*)(o + 64)  = HIp;
                        *(uint32_t*)(o + 128) = LOp;
                    } else if (sec == 1) {
                        __half* o = hk + hb * 192 + d;
                        *(uint32_t*)(o)       = HIp;
                        *(uint32_t*)(o + 64)  = LOp;
                        *(uint32_t*)(o + 128) = HIp;
                    } else {
                        *(uint32_t*)(hv + hb * 64 + d) = HIp;
                    }
                }
            }
        }
    }
}

// ---------------------------------------------------------------------------
// 5) fused flash attention (fp16 tensor core), writes d_ao1 (fp16 1-term)
//    grid (qt=16, bh=128), 128 threads
// ---------------------------------------------------------------------------
#define QSTR 400
#define VSTR 144
#define FL_QOFF 0
#define FL_KOFF 25600
#define FL_VOFF 76800
#define FLASH_SMEM 95232

__global__ __launch_bounds__(128) void k_flash(
        const __half* __restrict__ q3h, const __half* __restrict__ k3h,
        const __half* __restrict__ vhh, __half* __restrict__ ao1) {
    extern __shared__ char smem[];
    uint32_t sb = smem_u32(smem);
    int tid = threadIdx.x, lane = tid & 31, w = tid >> 5;
    int qt = blockIdx.x, bh = blockIdx.y;
    int b = bh >> 4, h = bh & 15;
    const __half* qg = q3h + (size_t)bh * L_ * 192 + (size_t)(qt * 64) * 192;
    const __half* kg = k3h + (size_t)bh * L_ * 192;
    const __half* vg = vhh + (size_t)bh * L_ * 64;

    int lrow2 = tid >> 1;
    int lhalf = tid & 1;

    {
        uint32_t qs = sb + FL_QOFF + lrow2 * QSTR + lhalf * 192;
        const char* src = (const char*)(qg + (size_t)lrow2 * 192) + lhalf * 192;
        #pragma unroll
        for (int i = 0; i < 12; i++) cp16(qs + i * 16, src + i * 16);
    }
    auto loadKV = [&](int t, int buf) {
        uint32_t ks = sb + FL_KOFF + buf * 25600 + lrow2 * QSTR + lhalf * 192;
        const char* ksrc = (const char*)(kg + (size_t)(t * 64 + lrow2) * 192) + lhalf * 192;
        #pragma unroll
        for (int i = 0; i < 12; i++) cp16(ks + i * 16, ksrc + i * 16);
        uint32_t vs = sb + FL_VOFF + buf * 9216 + lrow2 * VSTR + lhalf * 64;
        const char* vsrc = (const char*)(vg + (size_t)(t * 64 + lrow2) * 64) + lhalf * 64;
        #pragma unroll
        for (int i = 0; i < 4; i++) cp16(vs + i * 16, vsrc + i * 16);
    };
    loadKV(0, 0); cp_commit();
    loadKV(1, 1); cp_commit();

    float qm[2] = {-1e30f, -1e30f};
    float ll[2] = {0.f, 0.f};
    float o[8][4] = {};
    uint32_t qf[12][4];
    uint32_t aAddrQ = sb + FL_QOFF + (w * 16 + (lane & 15)) * QSTR + (lane >> 4) * 16;
    uint32_t bOffK = ((lane & 7) + ((lane >> 4) & 1) * 8) * QSTR + ((lane >> 3) & 1) * 16;
    uint32_t vOffT = (lane & 15) * VSTR + (lane >> 4) * 16;

    for (int t = 0; t < 16; t++) {
        if (t < 15) cp_wait1(); else cp_wait0();
        __syncthreads();
        if (t == 0) {
            #pragma unroll
            for (int ks = 0; ks < 12; ks++) ldsm4(qf[ks], aAddrQ + ks * 32);
        }
        uint32_t Kb = sb + FL_KOFF + (t & 1) * 25600;
        uint32_t Vb = sb + FL_VOFF + (t & 1) * 9216;

        float s[8][4] = {};
        #pragma unroll
        for (int ks = 0; ks < 12; ks++) {
            #pragma unroll
            for (int nb2 = 0; nb2 < 4; nb2++) {
                uint32_t bf[4];
                ldsm4(bf, Kb + bOffK + nb2 * 16 * QSTR + ks * 32);
                mma_f16(s[nb2 * 2],     qf[ks], bf[0], bf[1]);
                mma_f16(s[nb2 * 2 + 1], qf[ks], bf[2], bf[3]);
            }
        }
        float mx0 = -1e30f, mx1 = -1e30f;
        #pragma unroll
        for (int nb = 0; nb < 8; nb++) {
            #pragma unroll
            for (int e = 0; e < 4; e++) s[nb][e] *= 0.125f;
            mx0 = fmaxf(mx0, fmaxf(s[nb][0], s[nb][1]));
            mx1 = fmaxf(mx1, fmaxf(s[nb][2], s[nb][3]));
        }
        mx0 = fmaxf(mx0, __shfl_xor_sync(0xffffffffu, mx0, 1));
        mx0 = fmaxf(mx0, __shfl_xor_sync(0xffffffffu, mx0, 2));
        mx1 = fmaxf(mx1, __shfl_xor_sync(0xffffffffu, mx1, 1));
        mx1 = fmaxf(mx1, __shfl_xor_sync(0xffffffffu, mx1, 2));
        float mn0 = fmaxf(qm[0], mx0), mn1 = fmaxf(qm[1], mx1);
        float cf0 = __expf(qm[0] - mn0), cf1 = __expf(qm[1] - mn1);
        qm[0] = mn0; qm[1] = mn1;
        float sum0 = 0.f, sum1 = 0.f;
        #pragma unroll
        for (int nb = 0; nb < 8; nb++) {
            s[nb][0] = __expf(s[nb][0] - mn0);
            s[nb][1] = __expf(s[nb][1] - mn0);
            s[nb][2] = __expf(s[nb][2] - mn1);
            s[nb][3] = __expf(s[nb][3] - mn1);
            sum0 += s[nb][0] + s[nb][1];
            sum1 += s[nb][2] + s[nb][3];
        }
        sum0 += __shfl_xor_sync(0xffffffffu, sum0, 1);
        sum0 += __shfl_xor_sync(0xffffffffu, sum0, 2);
        sum1 += __shfl_xor_sync(0xffffffffu, sum1, 1);
        sum1 += __shfl_xor_sync(0xffffffffu, sum1, 2);
        ll[0] = ll[0] * cf0 + sum0;
        ll[1] = ll[1] * cf1 + sum1;
        #pragma unroll
        for (int nb = 0; nb < 8; nb++) {
            o[nb][0] *= cf0; o[nb][1] *= cf0;
            o[nb][2] *= cf1; o[nb][3] *= cf1;
        }
        uint32_t pf[4][4];
        #pragma unroll
        for (int kb = 0; kb < 4; kb++) {
            pf[kb][0] = packh(s[2 * kb][0],     s[2 * kb][1]);
            pf[kb][1] = packh(s[2 * kb][2],     s[2 * kb][3]);
            pf[kb][2] = packh(s[2 * kb + 1][0], s[2 * kb + 1][1]);
            pf[kb][3] = packh(s[2 * kb + 1][2], s[2 * kb + 1][3]);
        }
        #pragma unroll
        for (int kb = 0; kb < 4; kb++) {
            #pragma unroll
            for (int nbp = 0; nbp < 4; nbp++) {
                uint32_t vf[4];
                ldsm4t(vf, Vb + vOffT + kb * 16 * VSTR + nbp * 32);
                mma_f16(o[nbp * 2],     pf[kb], vf[0], vf[1]);
                mma_f16(o[nbp * 2 + 1], pf[kb], vf[2], vf[3]);
            }
        }
        __syncthreads();
        if (t + 2 < 16) { loadKV(t + 2, t & 1); cp_commit(); }
    }

    int g = lane >> 2;
    float inv0 = 1.f / ll[0], inv1 = 1.f / ll[1];
    int lr0 = qt * 64 + w * 16 + g;
    size_t base0 = ((size_t)(b * 1024 + lr0)) * D_ + h * 64;
    size_t base1 = ((size_t)(b * 1024 + lr0 + 8)) * D_ + h * 64;
    #pragma unroll
    for (int nb = 0; nb < 8; nb++) {
        int c = nb * 8 + (lane & 3) * 2;
        *(uint32_t*)(ao1 + base0 + c) = packh(o[nb][0] * inv0, o[nb][1] * inv0);
        *(uint32_t*)(ao1 + base1 + c) = packh(o[nb][2] * inv1, o[nb][3] * inv1);
    }
}

// ---------------------------------------------------------------------------
// Host launcher
// ---------------------------------------------------------------------------
extern "C" void kernel_launch(void* const* d_in, const int* in_sizes, int n_in,
                              void* d_out, int out_size) {
    const float* x     = (const float*)d_in[0];
    const float* t     = (const float*)d_in[1];
    const float* Wq    = (const float*)d_in[2];
    const float* Wk    = (const float*)d_in[3];
    const float* Wv    = (const float*)d_in[4];
    const float* Wo    = (const float*)d_in[5];
    const float* g1w   = (const float*)d_in[6];
    const float* g1b   = (const float*)d_in[7];
    const float* b1w   = (const float*)d_in[8];
    const float* b1b   = (const float*)d_in[9];
    const float* g2w   = (const float*)d_in[10];
    const float* g2b   = (const float*)d_in[11];
    const float* b2w   = (const float*)d_in[12];
    const float* b2b   = (const float*)d_in[13];
    const float* gatew = (const float*)d_in[14];
    const float* hidw  = (const float*)d_in[15];
    const float* outw  = (const float*)d_in[16];
    float* out = (float*)d_out;

    float *x1, *gate;
    __half *xn2, *ao1, *ga1, *wqkv2, *wo1, *wg2, *wh2, *wu1, *q3, *k3, *vh;
    cudaGetSymbolAddress((void**)&x1,    d_x1);
    cudaGetSymbolAddress((void**)&gate,  d_gate);
    cudaGetSymbolAddress((void**)&xn2,   d_xn2);
    cudaGetSymbolAddress((void**)&ao1,   d_ao1);
    cudaGetSymbolAddress((void**)&ga1,   d_ga1);
    cudaGetSymbolAddress((void**)&q3,    d_q3);
    cudaGetSymbolAddress((void**)&k3,    d_k3);
    cudaGetSymbolAddress((void**)&vh,    d_vh);
    cudaGetSymbolAddress((void**)&wqkv2, d_wqkv2);
    cudaGetSymbolAddress((void**)&wo1,   d_wo1);
    cudaGetSymbolAddress((void**)&wg2,   d_wg2);
    cudaGetSymbolAddress((void**)&wh2,   d_wh2);
    cudaGetSymbolAddress((void**)&wu1,   d_wu1);

    cudaFuncSetAttribute(k_gemm_mma<0>, cudaFuncAttributeMaxDynamicSharedMemorySize, GEMM_SMEM);
    cudaFuncSetAttribute(k_gemm_mma<1>, cudaFuncAttributeMaxDynamicSharedMemorySize, GEMM_SMEM);
    cudaFuncSetAttribute(k_gemm_mma<2>, cudaFuncAttributeMaxDynamicSharedMemorySize, GEMM_SMEM);
    cudaFuncSetAttribute(k_flash, cudaFuncAttributeMaxDynamicSharedMemorySize, FLASH_SMEM);

    // all weight conversions in one launch (4M float4s)
    k_cvtw<<<16384, 256>>>(Wq, Wk, Wv, Wo, gatew, hidw, outw,
                           wqkv2, wo1, wg2, wh2, wu1);

    // gamma/beta + norm1
    k_gamma_beta<<<128, 256>>>(t, g1w, g1b, b1w, b1b, g2w, g2b, b2w, b2b);
    k_rmsnorm_cvt<<<ROWS_, 256>>>(x, xn2, 0, 1);

    // fused QKV projection -> per-head fp16 flash operands (MODE 2)
    dim3 gqkv(3 * D_ / 128, ROWS_ / 128);   // (24, 64)
    dim3 gn1024(D_ / 128, ROWS_ / 128);     // (8, 64)
    dim3 gn4096(HID_ / 128, ROWS_ / 128);   // (32, 64)
    k_gemm_mma<2><<<gqkv, 256, GEMM_SMEM>>>(xn2, wqkv2, nullptr, nullptr, nullptr,
                                            q3, k3, vh, 3 * D_, K2D_);

    // flash attention (writes ao1 directly)
    k_flash<<<dim3(L_ / 64, BH_), 128, FLASH_SMEM>>>(q3, k3, vh, ao1);

    // output projection + residual (plain fp16, K = D)
    k_gemm_mma<0><<<gn1024, 256, GEMM_SMEM>>>(ao1, wo1, x, x1, nullptr,
                                              nullptr, nullptr, nullptr, D_, D_);

    // norm2 + MLP (swiglu fused into hid GEMM epilogue; out GEMM plain fp16, K = HID)
    k_rmsnorm_cvt<<<ROWS_, 256>>>(x1, xn2, 2, 3);
    k_gemm_mma<0><<<gn4096, 256, GEMM_SMEM>>>(xn2, wg2, nullptr, gate, nullptr,
                                              nullptr, nullptr, nullptr, HID_, K2D_);
    k_gemm_mma<1><<<gn4096, 256, GEMM_SMEM>>>(xn2, wh2, gate, nullptr, ga1,
                                              nullptr, nullptr, nullptr, HID_, K2D_);
    k_gemm_mma<0><<<gn1024, 256, GEMM_SMEM>>>(ga1, wu1, x1, out, nullptr,
                                              nullptr, nullptr, nullptr, D_, HID_);
}